// round 10
// baseline (speedup 1.0000x reference)
#include <cuda_runtime.h>

// QLSTM closed form:
//   qgate(x, p)[:, w] = prod_{j<=w} cos(p[j,1]) * cos(y[:,j] + p[j,0])
// LSTM cell + residual + layernorm; sequential over T only, independent per row.

#define TT 128
#define BB 256
#define DD 64
#define HH 10
#define G4 40   // 4 gates * H
#define WROW (DD + HH)   // 74: row stride of Wg

// Layout: pre[b][t][c], c = g*10 + w  (row-contiguous; warp streams 20KB/row)
__device__ float g_pre[BB * TT * G4];

__device__ __forceinline__ float tanh_fast(float x) {
    float y;
    asm("tanh.approx.f32 %0, %1;" : "=f"(y) : "f"(x));
    return y;
}
__device__ __forceinline__ float sig_fast(float x) {
    return fmaf(0.5f, tanh_fast(0.5f * x), 0.5f);
}

// ---------------------------------------------------------------------------
// Kernel 1 (proven, unchanged): pre[b][t][:] = fold_bias + x[t,b,:] @ Wg^T
// fold_bias = b_g[w] + p_g[w,0] + sum_j lnb_j * Whh_g[w,j]
// Store layout: pr[l] (l<32) = channels 0..31; pr[32+l] (l<8) = channels 32..39.
// Channel c = g*10+w for all four gates.
// ---------------------------------------------------------------------------
__global__ void __launch_bounds__(128) k_pre(
    const float* __restrict__ x,
    const float* __restrict__ Wf, const float* __restrict__ bf, const float* __restrict__ pf,
    const float* __restrict__ Wi, const float* __restrict__ bi, const float* __restrict__ pi,
    const float* __restrict__ Wu, const float* __restrict__ bu, const float* __restrict__ pu,
    const float* __restrict__ Wo, const float* __restrict__ bo, const float* __restrict__ po,
    const float* __restrict__ lnb_)
{
    int tid  = threadIdx.x;
    int warp = tid >> 5, l = tid & 31;
    int wg   = blockIdx.x * 4 + warp;     // 0..4095
    int b    = wg & (BB - 1);
    int tg   = wg >> 8;                    // 0..15
    int tbase = tg * 8;

    int g0 = l / 10, w0 = l - g0 * 10;
    const float* Wg0 = (g0 == 0) ? Wf : (g0 == 1) ? Wi : (g0 == 2) ? Wu : Wo;
    const float* bg0 = (g0 == 0) ? bf : (g0 == 1) ? bi : (g0 == 2) ? bu : bo;
    const float* pg0 = (g0 == 0) ? pf : (g0 == 1) ? pi : (g0 == 2) ? pu : po;

    float wa[DD];
    #pragma unroll
    for (int d = 0; d < DD; d++) wa[d] = Wg0[w0 * WROW + d];
    float bias0 = bg0[w0] + pg0[w0 * 3 + 0];
    #pragma unroll
    for (int j = 0; j < HH; j++)
        bias0 = fmaf(lnb_[j], Wg0[w0 * WROW + DD + j], bias0);

    float wb[DD];
    float bias1 = 0.f;
    int w1 = 2 + l;
    #pragma unroll
    for (int d = 0; d < DD; d++) wb[d] = (l < 8) ? Wo[w1 * WROW + d] : 0.f;
    if (l < 8) {
        bias1 = bo[w1] + po[w1 * 3 + 0];
        #pragma unroll
        for (int j = 0; j < HH; j++)
            bias1 = fmaf(lnb_[j], Wo[w1 * WROW + DD + j], bias1);
    }

    for (int i = 0; i < 8; i++) {
        int t = tbase + i;
        const float* xr = x + ((size_t)t * BB + b) * DD;
        float x0 = xr[l];
        float x1 = xr[l + 32];

        float a0 = bias0, a0b = 0.f;
        float a1 = bias1, a1b = 0.f;
        #pragma unroll
        for (int d = 0; d < 32; d += 2) {
            float xd0 = __shfl_sync(0xffffffffu, x0, d);
            float xd1 = __shfl_sync(0xffffffffu, x0, d + 1);
            a0  = fmaf(xd0, wa[d], a0);
            a0b = fmaf(xd1, wa[d + 1], a0b);
            a1  = fmaf(xd0, wb[d], a1);
            a1b = fmaf(xd1, wb[d + 1], a1b);
        }
        #pragma unroll
        for (int d = 0; d < 32; d += 2) {
            float xd0 = __shfl_sync(0xffffffffu, x1, d);
            float xd1 = __shfl_sync(0xffffffffu, x1, d + 1);
            a0  = fmaf(xd0, wa[32 + d], a0);
            a0b = fmaf(xd1, wa[32 + d + 1], a0b);
            a1  = fmaf(xd0, wb[32 + d], a1);
            a1b = fmaf(xd1, wb[32 + d + 1], a1b);
        }
        float* pr = g_pre + ((size_t)b * TT + t) * G4;
        pr[l] = a0 + a0b;
        if (l < 8) pr[32 + l] = a1 + a1b;
    }
}

// ---------------------------------------------------------------------------
// Kernel 2: one warp per row (1 warp/SMSP — established optimum).
// NEW: no shared memory, no syncwarp. Prefix products via segmented shuffle
// scan:
//   ch0: lane l = gate l/10, wire l%10 (lanes 0..29; 30,31 garbage)
//   ch1: lane l = gate 3,     wire l    (lanes 0..9;  rest garbage)
// Inclusive product scan over 10-wide segments: 4 rounds shfl.up+SEL+MUL,
// both channels interleaved. Gate1/2 values fetched with 2 shfl.idx.
// ---------------------------------------------------------------------------
__global__ void __launch_bounds__(64) k_scan(
    const float* __restrict__ Wf, const float* __restrict__ pf,
    const float* __restrict__ Wi, const float* __restrict__ pi,
    const float* __restrict__ Wu, const float* __restrict__ pu,
    const float* __restrict__ Wo, const float* __restrict__ po,
    const float* __restrict__ lng_, const float* __restrict__ lnb_,
    float* __restrict__ out)
{
    int tid  = threadIdx.x;
    int warp = tid >> 5, l = tid & 31;
    int row  = blockIdx.x * 2 + warp;

    // ch0: lanes 0..29 -> gate g0 = l/10, wire w0 = l%10; lanes 30,31 dummy
    int g0c = l / 10;                 // 3 for lanes 30,31
    int g0 = (g0c > 2) ? 2 : g0c;     // clamp for safe pointer selection
    int w0 = l - g0c * 10;
    const float* Wg0 = (g0 == 0) ? Wf : (g0 == 1) ? Wi : Wu;
    const float* Pg0 = (g0 == 0) ? pf : (g0 == 1) ? pi : pu;

    float cth1_0 = cosf(Pg0[w0 * 3 + 1]);
    float whh0[HH], sw0 = 0.f;
    #pragma unroll
    for (int j = 0; j < HH; j++) {
        whh0[j] = Wg0[w0 * WROW + DD + j] * lng_[j];
        sw0 += whh0[j];
    }

    // ch1: lanes 0..9 -> gate 3 wire l
    int w1 = (l < HH) ? l : 0;
    float cth1_1 = cosf(po[w1 * 3 + 1]);
    float whh1[HH], sw1 = 0.f;
    #pragma unroll
    for (int j = 0; j < HH; j++) {
        whh1[j] = Wo[w1 * WROW + DD + j] * lng_[j];
        sw1 += whh1[j];
    }

    float lng_l = 0.f, lnb_l = 0.f;
    if (l < HH) { lng_l = lng_[l]; lnb_l = lnb_[l]; }

    int seg0 = g0c * 10;              // segment start for ch0 scan

    float hr[HH];
    #pragma unroll
    for (int j = 0; j < HH; j++) hr[j] = 0.f;
    float mu = 0.f, rs = 0.f, hown = 0.f, creg = 0.f;

    const float* prow = g_pre + (size_t)row * TT * G4;
    float preA0 = prow[l];                                  // ch 0..31 (30,31 unused-garbage ok)
    float preA1 = (l < HH) ? prow[30 + l] : 0.f;            // gate3 ch
    float preB0 = prow[G4 + l];
    float preB1 = (l < HH) ? prow[G4 + 30 + l] : 0.f;

    float* outp = out + (size_t)row * HH;
    const size_t ostride = (size_t)BB * HH;

#define STEP_BODY(PF0, PF1)                                                     \
    {                                                                           \
        float a0 = 0.f, a1 = 0.f, a2 = 0.f, a3 = 0.f;                           \
        float c0 = 0.f, c1 = 0.f, c2 = 0.f, c3 = 0.f;                           \
        a0 = fmaf(hr[0], whh0[0], a0);  c0 = fmaf(hr[0], whh1[0], c0);          \
        a1 = fmaf(hr[1], whh0[1], a1);  c1 = fmaf(hr[1], whh1[1], c1);          \
        a2 = fmaf(hr[2], whh0[2], a2);  c2 = fmaf(hr[2], whh1[2], c2);          \
        a3 = fmaf(hr[3], whh0[3], a3);  c3 = fmaf(hr[3], whh1[3], c3);          \
        a0 = fmaf(hr[4], whh0[4], a0);  c0 = fmaf(hr[4], whh1[4], c0);          \
        a1 = fmaf(hr[5], whh0[5], a1);  c1 = fmaf(hr[5], whh1[5], c1);          \
        a2 = fmaf(hr[6], whh0[6], a2);  c2 = fmaf(hr[6], whh1[6], c2);          \
        a3 = fmaf(hr[7], whh0[7], a3);  c3 = fmaf(hr[7], whh1[7], c3);          \
        a0 = fmaf(hr[8], whh0[8], a0);  c0 = fmaf(hr[8], whh1[8], c0);          \
        a1 = fmaf(hr[9], whh0[9], a1);  c1 = fmaf(hr[9], whh1[9], c1);          \
        float dot0 = (a0 + a1) + (a2 + a3);                                     \
        float dot1 = (c0 + c1) + (c2 + c3);                                     \
        float y0 = fmaf(rs, fmaf(-mu, sw0, dot0), preA0);                       \
        float y1 = fmaf(rs, fmaf(-mu, sw1, dot1), preA1);                       \
        float q0 = cth1_0 * __cosf(y0);                                         \
        float q1 = cth1_1 * __cosf(y1);                                         \
        /* segmented inclusive product scans (both channels interleaved) */     \
        {                                                                       \
            float v0, v1;                                                       \
            v0 = __shfl_up_sync(0xffffffffu, q0, 1);                            \
            v1 = __shfl_up_sync(0xffffffffu, q1, 1);                            \
            q0 *= (l - 1 >= seg0) ? v0 : 1.f;                                   \
            q1 *= (l >= 1) ? v1 : 1.f;                                          \
            v0 = __shfl_up_sync(0xffffffffu, q0, 2);                            \
            v1 = __shfl_up_sync(0xffffffffu, q1, 2);                            \
            q0 *= (l - 2 >= seg0) ? v0 : 1.f;                                   \
            q1 *= (l >= 2) ? v1 : 1.f;                                          \
            v0 = __shfl_up_sync(0xffffffffu, q0, 4);                            \
            v1 = __shfl_up_sync(0xffffffffu, q1, 4);                            \
            q0 *= (l - 4 >= seg0) ? v0 : 1.f;                                   \
            q1 *= (l >= 4) ? v1 : 1.f;                                          \
            v0 = __shfl_up_sync(0xffffffffu, q0, 8);                            \
            v1 = __shfl_up_sync(0xffffffffu, q1, 8);                            \
            q0 *= (l - 8 >= seg0) ? v0 : 1.f;                                   \
            q1 *= (l >= 8) ? v1 : 1.f;                                          \
        }                                                                       \
        /* gate values at lane w (w = l < 10): f = q0 (own lane), o = q1 */     \
        float pI = __shfl_sync(0xffffffffu, q0, (l < HH) ? (10 + l) : l);       \
        float pU = __shfl_sync(0xffffffffu, q0, (l < HH) ? (20 + l) : l);       \
        float fg = sig_fast(q0);                                                \
        float ig = sig_fast(pI);                                                \
        float gg = tanh_fast(pU);                                               \
        float og = sig_fast(q1);                                                \
        creg = fmaf(fg, creg, ig * gg);                                         \
        float hval = fmaf(og, tanh_fast(creg), hown);                           \
        _Pragma("unroll")                                                       \
        for (int j = 0; j < HH; j++) hr[j] = __shfl_sync(0xffffffffu, hval, j); \
        float sA = 0.f, sB = 0.f, qA = 0.f, qB = 0.f;                           \
        _Pragma("unroll")                                                       \
        for (int j = 0; j < HH; j += 2) {                                       \
            sA += hr[j];                                                        \
            sB += hr[j + 1];                                                    \
            qA = fmaf(hr[j],     hr[j],     qA);                                \
            qB = fmaf(hr[j + 1], hr[j + 1], qB);                                \
        }                                                                       \
        mu = (sA + sB) * 0.1f;                                                  \
        rs = rsqrtf(fmaf(-mu, mu, (qA + qB) * 0.1f) + 1e-5f);                   \
        hown = fmaf((hval - mu) * rs, lng_l, lnb_l);                            \
        if (l < HH) outp[l] = hown;                                             \
        outp += ostride;                                                        \
        preA0 = preB0; preA1 = preB1;                                           \
        preB0 = (PF0); preB1 = (PF1);                                           \
    }

    #pragma unroll 2
    for (int t = 0; t < TT - 2; t++) {
        const float* pn = prow + (size_t)(t + 2) * G4;
        float preC0 = pn[l];
        float preC1 = (l < HH) ? pn[30 + l] : 0.f;
        STEP_BODY(preC0, preC1)
    }
    for (int t = TT - 2; t < TT; t++) {
        STEP_BODY(0.f, 0.f)
    }
#undef STEP_BODY

    if (l < HH) {
        out[(size_t)TT * BB * HH + (size_t)row * HH + l]           = hown;
        out[(size_t)TT * BB * HH + (size_t)BB * HH + row * HH + l] = creg;
    }
}

extern "C" void kernel_launch(void* const* d_in, const int* in_sizes, int n_in,
                              void* d_out, int out_size)
{
    const float* x   = (const float*)d_in[0];
    const float* Wf  = (const float*)d_in[1];
    const float* bf  = (const float*)d_in[2];
    const float* pf  = (const float*)d_in[3];
    const float* Wi  = (const float*)d_in[4];
    const float* bi  = (const float*)d_in[5];
    const float* pi_ = (const float*)d_in[6];
    const float* Wu  = (const float*)d_in[7];
    const float* bu  = (const float*)d_in[8];
    const float* pu  = (const float*)d_in[9];
    const float* Wo  = (const float*)d_in[10];
    const float* bo  = (const float*)d_in[11];
    const float* po  = (const float*)d_in[12];
    const float* lng = (const float*)d_in[13];
    const float* lnb = (const float*)d_in[14];

    k_pre<<<1024, 128>>>(x, Wf, bf, pf, Wi, bi, pi_, Wu, bu, pu, Wo, bo, po, lnb);
    k_scan<<<BB / 2, 64>>>(Wf, pf, Wi, pi_, Wu, pu, Wo, po, lng, lnb, (float*)d_out);
}

// round 11
// speedup vs baseline: 1.1580x; 1.1580x over previous
#include <cuda_runtime.h>

// QLSTM closed form:
//   qgate(x, p)[:, w] = prod_{j<=w} cos(p[j,1]) * cos(y[:,j] + p[j,0])
// LSTM cell + residual + layernorm; sequential over T only, independent per row.

#define TT 128
#define BB 256
#define DD 64
#define HH 10
#define G4 40   // 4 gates * H
#define WROW (DD + HH)   // 74: row stride of Wg

// Layout: pre[b][t][c], c = g*10 + w  (row-contiguous; warp streams 20KB/row)
__device__ float g_pre[BB * TT * G4];

__device__ __forceinline__ float tanh_fast(float x) {
    float y;
    asm("tanh.approx.f32 %0, %1;" : "=f"(y) : "f"(x));
    return y;
}

// ---------------------------------------------------------------------------
// Kernel 1 (proven, unchanged): pre[b][t][:] = fold_bias + x[t,b,:] @ Wg^T
// fold_bias = b_g[w] + p_g[w,0] + sum_j lnb_j * Whh_g[w,j]
// ---------------------------------------------------------------------------
__global__ void __launch_bounds__(128) k_pre(
    const float* __restrict__ x,
    const float* __restrict__ Wf, const float* __restrict__ bf, const float* __restrict__ pf,
    const float* __restrict__ Wi, const float* __restrict__ bi, const float* __restrict__ pi,
    const float* __restrict__ Wu, const float* __restrict__ bu, const float* __restrict__ pu,
    const float* __restrict__ Wo, const float* __restrict__ bo, const float* __restrict__ po,
    const float* __restrict__ lnb_)
{
    int tid  = threadIdx.x;
    int warp = tid >> 5, l = tid & 31;
    int wg   = blockIdx.x * 4 + warp;     // 0..4095
    int b    = wg & (BB - 1);
    int tg   = wg >> 8;                    // 0..15
    int tbase = tg * 8;

    int g0 = l / 10, w0 = l - g0 * 10;
    const float* Wg0 = (g0 == 0) ? Wf : (g0 == 1) ? Wi : (g0 == 2) ? Wu : Wo;
    const float* bg0 = (g0 == 0) ? bf : (g0 == 1) ? bi : (g0 == 2) ? bu : bo;
    const float* pg0 = (g0 == 0) ? pf : (g0 == 1) ? pi : (g0 == 2) ? pu : po;

    float wa[DD];
    #pragma unroll
    for (int d = 0; d < DD; d++) wa[d] = Wg0[w0 * WROW + d];
    float bias0 = bg0[w0] + pg0[w0 * 3 + 0];
    #pragma unroll
    for (int j = 0; j < HH; j++)
        bias0 = fmaf(lnb_[j], Wg0[w0 * WROW + DD + j], bias0);

    float wb[DD];
    float bias1 = 0.f;
    int w1 = 2 + l;
    #pragma unroll
    for (int d = 0; d < DD; d++) wb[d] = (l < 8) ? Wo[w1 * WROW + d] : 0.f;
    if (l < 8) {
        bias1 = bo[w1] + po[w1 * 3 + 0];
        #pragma unroll
        for (int j = 0; j < HH; j++)
            bias1 = fmaf(lnb_[j], Wo[w1 * WROW + DD + j], bias1);
    }

    for (int i = 0; i < 8; i++) {
        int t = tbase + i;
        const float* xr = x + ((size_t)t * BB + b) * DD;
        float x0 = xr[l];
        float x1 = xr[l + 32];

        float a0 = bias0, a0b = 0.f;
        float a1 = bias1, a1b = 0.f;
        #pragma unroll
        for (int d = 0; d < 32; d += 2) {
            float xd0 = __shfl_sync(0xffffffffu, x0, d);
            float xd1 = __shfl_sync(0xffffffffu, x0, d + 1);
            a0  = fmaf(xd0, wa[d], a0);
            a0b = fmaf(xd1, wa[d + 1], a0b);
            a1  = fmaf(xd0, wb[d], a1);
            a1b = fmaf(xd1, wb[d + 1], a1b);
        }
        #pragma unroll
        for (int d = 0; d < 32; d += 2) {
            float xd0 = __shfl_sync(0xffffffffu, x1, d);
            float xd1 = __shfl_sync(0xffffffffu, x1, d + 1);
            a0  = fmaf(xd0, wa[32 + d], a0);
            a0b = fmaf(xd1, wa[32 + d + 1], a0b);
            a1  = fmaf(xd0, wb[32 + d], a1);
            a1b = fmaf(xd1, wb[32 + d + 1], a1b);
        }
        float* pr = g_pre + ((size_t)b * TT + t) * G4;
        pr[l] = a0 + a0b;
        if (l < 8) pr[32 + l] = a1 + a1b;
    }
}

// ---------------------------------------------------------------------------
// Kernel 2: one warp per row, 1 warp/SMSP (established optimum), R9 base with
// a restructured gate section:
//  - lane l computes ONLY its own gate's prefix (gate l/10, wire l%10) via
//    per-lane-segment LDS (3 loads) + 9 SEL + 9 MUL; second pass for gate o.
//  - wire-lane fetches gate i/u prefixes with 2 parallel shfl.idx.
//  - sigmoid 0.5 folded into cth1 of wire-0 channels of gates f,i,o.
//  - y = fma(rs, dot, k) with k = pre - rs*mu*sw precomputed in LN shadow.
// qs layout per warp/parity: gate g segment at [g*12 .. g*12+9] (48 floats).
// ---------------------------------------------------------------------------
__global__ void __launch_bounds__(64) k_scan(
    const float* __restrict__ Wf, const float* __restrict__ pf,
    const float* __restrict__ Wi, const float* __restrict__ pi,
    const float* __restrict__ Wu, const float* __restrict__ pu,
    const float* __restrict__ Wo, const float* __restrict__ po,
    const float* __restrict__ lng_, const float* __restrict__ lnb_,
    float* __restrict__ out)
{
    __shared__ __align__(16) float qs[2][2][48];

    int tid  = threadIdx.x;
    int warp = tid >> 5, l = tid & 31;
    int row  = blockIdx.x * 2 + warp;

    // ch0: lane l -> channel l: gate g0 = l/10 (0..3), wire w0 = l%10
    // (lanes 30,31 = gate o wires 0,1)
    int g0 = l / 10, w0 = l - g0 * 10;
    const float* Wg0 = (g0 == 0) ? Wf : (g0 == 1) ? Wi : (g0 == 2) ? Wu : Wo;
    const float* Pg0 = (g0 == 0) ? pf : (g0 == 1) ? pi : (g0 == 2) ? pu : po;

    float cth1_0 = cosf(Pg0[w0 * 3 + 1]);
    // fold sigmoid's x/2 into wire-0 channel of sigmoid gates f (ch0), i (ch10), o (ch30)
    if (l == 0 || l == 10 || l == 30) cth1_0 *= 0.5f;
    float whh0[HH], sw0 = 0.f;
    #pragma unroll
    for (int j = 0; j < HH; j++) {
        whh0[j] = Wg0[w0 * WROW + DD + j] * lng_[j];
        sw0 += whh0[j];
    }

    // ch1: lanes 0..7 -> gate o wires 2..9 (channels 32..39)
    int w1 = 2 + l;
    float cth1_1 = 0.f, sw1 = 0.f;
    float whh1[HH];
    #pragma unroll
    for (int j = 0; j < HH; j++) whh1[j] = 0.f;
    if (l < 8) {
        cth1_1 = cosf(po[w1 * 3 + 1]);
        #pragma unroll
        for (int j = 0; j < HH; j++) {
            whh1[j] = Wo[w1 * WROW + DD + j] * lng_[j];
            sw1 += whh1[j];
        }
    }

    float lng_l = 0.f, lnb_l = 0.f;
    if (l < HH) { lng_l = lng_[l]; lnb_l = lnb_[l]; }

    int sb = g0 * 12;     // own-gate segment base (floats) for the tree

    float hr[HH];
    #pragma unroll
    for (int j = 0; j < HH; j++) hr[j] = 0.f;
    float mu = 0.f, rs = 0.f, hown = 0.f, creg = 0.f;

    const float* prow = g_pre + (size_t)row * TT * G4;
    float preA0 = prow[l];
    float preA1 = (l < 8) ? prow[32 + l] : 0.f;
    float preB0 = prow[G4 + l];
    float preB1 = (l < 8) ? prow[G4 + 32 + l] : 0.f;
    float k0 = preA0, k1 = preA1;     // rs = mu = 0 at t=0

    float* outp = out + (size_t)row * HH;
    const size_t ostride = (size_t)BB * HH;

#define STEP_BODY(PF0, PF1)                                                     \
    {                                                                           \
        float a0 = 0.f, a1 = 0.f, a2 = 0.f, a3 = 0.f;                           \
        float c0 = 0.f, c1 = 0.f, c2 = 0.f, c3 = 0.f;                           \
        a0 = fmaf(hr[0], whh0[0], a0);  c0 = fmaf(hr[0], whh1[0], c0);          \
        a1 = fmaf(hr[1], whh0[1], a1);  c1 = fmaf(hr[1], whh1[1], c1);          \
        a2 = fmaf(hr[2], whh0[2], a2);  c2 = fmaf(hr[2], whh1[2], c2);          \
        a3 = fmaf(hr[3], whh0[3], a3);  c3 = fmaf(hr[3], whh1[3], c3);          \
        a0 = fmaf(hr[4], whh0[4], a0);  c0 = fmaf(hr[4], whh1[4], c0);          \
        a1 = fmaf(hr[5], whh0[5], a1);  c1 = fmaf(hr[5], whh1[5], c1);          \
        a2 = fmaf(hr[6], whh0[6], a2);  c2 = fmaf(hr[6], whh1[6], c2);          \
        a3 = fmaf(hr[7], whh0[7], a3);  c3 = fmaf(hr[7], whh1[7], c3);          \
        a0 = fmaf(hr[8], whh0[8], a0);  c0 = fmaf(hr[8], whh1[8], c0);          \
        a1 = fmaf(hr[9], whh0[9], a1);  c1 = fmaf(hr[9], whh1[9], c1);          \
        float dot0 = (a0 + a1) + (a2 + a3);                                     \
        float dot1 = (c0 + c1) + (c2 + c3);                                     \
        float y0 = fmaf(rs, dot0, k0);                                          \
        float y1 = fmaf(rs, dot1, k1);                                          \
        float q0 = cth1_0 * __cosf(y0);                                         \
        float q1 = cth1_1 * __cosf(y1);                                         \
        int par = t & 1;                                                        \
        qs[warp][par][g0 * 12 + w0] = q0;                                       \
        if (l < 8) qs[warp][par][36 + w1] = q1;                                 \
        __syncwarp();                                                           \
        /* tree 1: own-gate prefix (lane group g0, masks on w0) */              \
        const float* seg = &qs[warp][par][sb];                                  \
        float4 va = *(const float4*)seg;                                        \
        float4 vb = *(const float4*)(seg + 4);                                  \
        float2 vc = *(const float2*)(seg + 8);                                  \
        float m1 = va.x * ((w0 >= 1) ? va.y : 1.f);                             \
        float m2 = ((w0 >= 2) ? va.z : 1.f) * ((w0 >= 3) ? va.w : 1.f);         \
        float m3 = ((w0 >= 4) ? vb.x : 1.f) * ((w0 >= 5) ? vb.y : 1.f);         \
        float m4 = ((w0 >= 6) ? vb.z : 1.f) * ((w0 >= 7) ? vb.w : 1.f);         \
        float m5 = ((w0 >= 8) ? vc.x : 1.f) * ((w0 >= 9) ? vc.y : 1.f);         \
        float p1v = ((m1 * m2) * (m3 * m4)) * m5;                               \
        /* tree 2: gate-o prefix (all lanes, masks on w0; lanes 0..9 valid) */  \
        const float* seg3 = &qs[warp][par][36];                                 \
        float4 ua = *(const float4*)seg3;                                       \
        float4 ub = *(const float4*)(seg3 + 4);                                 \
        float2 uc = *(const float2*)(seg3 + 8);                                 \
        float n1 = ua.x * ((w0 >= 1) ? ua.y : 1.f);                             \
        float n2 = ((w0 >= 2) ? ua.z : 1.f) * ((w0 >= 3) ? ua.w : 1.f);         \
        float n3 = ((w0 >= 4) ? ub.x : 1.f) * ((w0 >= 5) ? ub.y : 1.f);         \
        float n4 = ((w0 >= 6) ? ub.z : 1.f) * ((w0 >= 7) ? ub.w : 1.f);         \
        float n5 = ((w0 >= 8) ? uc.x : 1.f) * ((w0 >= 9) ? uc.y : 1.f);         \
        float p2v = ((n1 * n2) * (n3 * n4)) * n5;                               \
        float pI = __shfl_sync(0xffffffffu, p1v, l + 10);                       \
        float pU = __shfl_sync(0xffffffffu, p1v, l + 20);                       \
        float fg = fmaf(0.5f, tanh_fast(p1v), 0.5f);                            \
        float ig = fmaf(0.5f, tanh_fast(pI),  0.5f);                            \
        float gg = tanh_fast(pU);                                               \
        float og = fmaf(0.5f, tanh_fast(p2v), 0.5f);                            \
        creg = fmaf(fg, creg, ig * gg);                                         \
        float hval = fmaf(og, tanh_fast(creg), hown);                           \
        _Pragma("unroll")                                                       \
        for (int j = 0; j < HH; j++) hr[j] = __shfl_sync(0xffffffffu, hval, j); \
        float sA = 0.f, sB = 0.f, qA = 0.f, qB = 0.f;                           \
        _Pragma("unroll")                                                       \
        for (int j = 0; j < HH; j += 2) {                                       \
            sA += hr[j];                                                        \
            sB += hr[j + 1];                                                    \
            qA = fmaf(hr[j],     hr[j],     qA);                                \
            qB = fmaf(hr[j + 1], hr[j + 1], qB);                                \
        }                                                                       \
        mu = (sA + sB) * 0.1f;                                                  \
        rs = rsqrtf(fmaf(-mu, mu, (qA + qB) * 0.1f) + 1e-5f);                   \
        hown = fmaf((hval - mu) * rs, lng_l, lnb_l);                            \
        if (l < HH) outp[l] = hown;                                             \
        outp += ostride;                                                        \
        preA0 = preB0; preA1 = preB1;                                           \
        preB0 = (PF0); preB1 = (PF1);                                           \
        float rsmu = rs * mu;                                                   \
        k0 = fmaf(-rsmu, sw0, preA0);                                           \
        k1 = fmaf(-rsmu, sw1, preA1);                                           \
    }

    #pragma unroll 2
    for (int t = 0; t < TT - 2; t++) {
        const float* pn = prow + (size_t)(t + 2) * G4;
        float preC0 = pn[l];
        float preC1 = (l < 8) ? pn[32 + l] : 0.f;
        STEP_BODY(preC0, preC1)
    }
    for (int t = TT - 2; t < TT; t++) {
        STEP_BODY(0.f, 0.f)
    }
#undef STEP_BODY

    if (l < HH) {
        out[(size_t)TT * BB * HH + (size_t)row * HH + l]           = hown;
        out[(size_t)TT * BB * HH + (size_t)BB * HH + row * HH + l] = creg;
    }
}

extern "C" void kernel_launch(void* const* d_in, const int* in_sizes, int n_in,
                              void* d_out, int out_size)
{
    const float* x   = (const float*)d_in[0];
    const float* Wf  = (const float*)d_in[1];
    const float* bf  = (const float*)d_in[2];
    const float* pf  = (const float*)d_in[3];
    const float* Wi  = (const float*)d_in[4];
    const float* bi  = (const float*)d_in[5];
    const float* pi_ = (const float*)d_in[6];
    const float* Wu  = (const float*)d_in[7];
    const float* bu  = (const float*)d_in[8];
    const float* pu  = (const float*)d_in[9];
    const float* Wo  = (const float*)d_in[10];
    const float* bo  = (const float*)d_in[11];
    const float* po  = (const float*)d_in[12];
    const float* lng = (const float*)d_in[13];
    const float* lnb = (const float*)d_in[14];

    k_pre<<<1024, 128>>>(x, Wf, bf, pf, Wi, bi, pi_, Wu, bu, pu, Wo, bo, po, lnb);
    k_scan<<<BB / 2, 64>>>(Wf, pf, Wi, pi_, Wu, pu, Wo, po, lng, lnb, (float*)d_out);
}